// round 2
// baseline (speedup 1.0000x reference)
#include <cuda_runtime.h>
#include <math.h>
#include <float.h>
#include <stdint.h>

#define BB 8
#define TT 256
#define KK 20
#define HH 768
#define VV 30522
#define G4 3072
#define TM1 255
#define MR 2040          // (T-1)*B
#define NTILE2 239       // ceil(V/128)
#define LSTM_NB 96
#define TAU_C 1.0f

// ------------- static device scratch -------------
__device__ float g_em[TT*BB*KK];
__device__ float g_trans[KK*KK];
__device__ float g_alphas[TT*BB*KK];
__device__ float g_relaxed[TT*BB*KK];
__device__ int   g_z[TT*BB];
__device__ float g_enttok[BB*TT];
__device__ float g_din[MR*HH];
__device__ float g_xih[(size_t)MR*G4];
__device__ float g_wt2[HH*G4];
__device__ float g_hs[MR*HH];
__device__ float g_pmax[(size_t)MR*NTILE2];
__device__ float g_psum[(size_t)MR*NTILE2];
__device__ float g_tgtlog[MR];
__device__ float g_tokpl[MR];
__device__ int   g_tgt[MR];
__device__ float g_maskt[MR];
__device__ unsigned g_bar_cnt;
__device__ unsigned g_bar_gen;

// ------------- misc small kernels -------------
__global__ void fillz_kernel(float* out, int n) {
    int i = blockIdx.x * 256 + threadIdx.x;
    if (i < n) out[i] = 0.f;
}

// emission[t][b][k] + entropy token
__global__ void emission_kernel(const float* __restrict__ x_emb,
                                const float* __restrict__ S,
                                const int* __restrict__ amask) {
    __shared__ float xs[HH];
    __shared__ float es[KK];
    int bt = blockIdx.x;          // b*T + t
    int b = bt >> 8, t = bt & 255;
    int tid = threadIdx.x;
    for (int i = tid; i < HH; i += 128) xs[i] = x_emb[(size_t)bt * HH + i];
    __syncthreads();
    int w = tid >> 5, lane = tid & 31;
    for (int k = w; k < KK; k += 4) {
        float s = 0.f;
        for (int i = lane; i < HH; i += 32) s += xs[i] * S[k * HH + i];
        #pragma unroll
        for (int o = 16; o; o >>= 1) s += __shfl_xor_sync(0xffffffffu, s, o);
        if (lane == 0) { g_em[(t * 8 + b) * KK + k] = s; es[k] = s; }
    }
    __syncthreads();
    if (tid == 0) {
        float m = -FLT_MAX;
        #pragma unroll
        for (int k = 0; k < KK; k++) m = fmaxf(m, es[k]);
        float ss = 0.f, dot = 0.f;
        #pragma unroll
        for (int k = 0; k < KK; k++) {
            float e = expf(es[k] - m);
            ss += e; dot += es[k] * e;
        }
        float lse = m + logf(ss);
        g_enttok[bt] = (lse - dot / ss) * (float)amask[bt];
    }
}

__global__ void trans_kernel(const float* __restrict__ S) {
    int idx = threadIdx.x;
    if (idx < KK * KK) {
        int i = idx / KK, j = idx % KK;
        float s = 0.f;
        for (int h = 0; h < HH; h++) s += S[i * HH + h] * S[j * HH + h];
        g_trans[idx] = s;
    }
}

// CRF forward + relaxed backward sampling (one block of 256)
__global__ void crf_kernel(const float* __restrict__ gumbel) {
    __shared__ float sa[BB*KK];
    __shared__ float st[KK*KK];
    int tid = threadIdx.x;
    for (int i = tid; i < KK * KK; i += 256) st[i] = g_trans[i];
    if (tid < BB * KK) { float v = g_em[tid]; sa[tid] = v; g_alphas[tid] = v; }
    __syncthreads();
    for (int t = 1; t < TT; t++) {
        float v = 0.f;
        if (tid < BB * KK) {
            int b = tid / KK, j = tid % KK;
            float m = -FLT_MAX;
            #pragma unroll
            for (int i = 0; i < KK; i++) m = fmaxf(m, sa[b * KK + i] + st[i * KK + j]);
            float s = 0.f;
            #pragma unroll
            for (int i = 0; i < KK; i++) s += expf(sa[b * KK + i] + st[i * KK + j] - m);
            v = m + logf(s) + g_em[t * (BB*KK) + tid];
        }
        __syncthreads();
        if (tid < BB * KK) { sa[tid] = v; g_alphas[t * (BB*KK) + tid] = v; }
        __syncthreads();
    }
    // backward sampling: warp b handles batch b
    int b = tid >> 5, lane = tid & 31;
    int znext = 0;
    for (int t = TT - 1; t >= 0; t--) {
        float a;
        if (t == TT - 1) a = (lane < KK) ? sa[b * KK + lane] : -FLT_MAX;
        else             a = (lane < KK) ? (g_alphas[t * (BB*KK) + b * KK + lane]
                                            + st[lane * KK + znext]) : -FLT_MAX;
        float m = a;
        #pragma unroll
        for (int o = 16; o; o >>= 1) m = fmaxf(m, __shfl_xor_sync(0xffffffffu, m, o));
        float e = (lane < KK) ? expf(a - m) : 0.f;
        float s = e;
        #pragma unroll
        for (int o = 16; o; o >>= 1) s += __shfl_xor_sync(0xffffffffu, s, o);
        float lse = m + logf(s);
        float gb = (lane < KK) ? gumbel[(t * BB + b) * KK + lane] : 0.f;
        float y = (lane < KK) ? (a - lse + gb) : -FLT_MAX;
        // argmax with first-index tie break
        float mv = y; int mi = (lane < KK) ? lane : 1000;
        #pragma unroll
        for (int o = 16; o; o >>= 1) {
            float ov = __shfl_xor_sync(0xffffffffu, mv, o);
            int   oi = __shfl_xor_sync(0xffffffffu, mi, o);
            if (ov > mv || (ov == mv && oi < mi)) { mv = ov; mi = oi; }
        }
        // relaxed = softmax(y / tau)
        float yt = y * (1.0f / TAU_C);
        float m2 = yt;
        #pragma unroll
        for (int o = 16; o; o >>= 1) m2 = fmaxf(m2, __shfl_xor_sync(0xffffffffu, m2, o));
        float e2 = (lane < KK) ? expf(yt - m2) : 0.f;
        float s2 = e2;
        #pragma unroll
        for (int o = 16; o; o >>= 1) s2 += __shfl_xor_sync(0xffffffffu, s2, o);
        if (lane < KK) g_relaxed[(t * BB + b) * KK + lane] = e2 / s2;
        if (lane == 0) g_z[t * BB + b] = mi;
        znext = mi;
    }
}

// dec_in row r=t*8+b : relaxed @ S + word_emb ; also targets / masks
__global__ void decin_kernel(const float* __restrict__ S,
                             const float* __restrict__ emb,
                             const int* __restrict__ x,
                             const int* __restrict__ amask) {
    __shared__ float rs[KK];
    int r = blockIdx.x;
    int t = r >> 3, b = r & 7;
    int tid = threadIdx.x;
    if (tid < KK) rs[tid] = g_relaxed[r * KK + tid];
    if (tid == 0) {
        g_tgt[r]   = x[b * TT + t + 1];
        g_maskt[r] = (float)amask[b * TT + t + 1];
    }
    __syncthreads();
    int xid = x[b * TT + t];
    for (int h = tid; h < HH; h += 256) {
        float s = emb[(size_t)xid * HH + h];
        #pragma unroll
        for (int k = 0; k < KK; k++) s += rs[k] * S[k * HH + h];
        g_din[(size_t)r * HH + h] = s;
    }
}

// W_hh^T, gate-interleaved: g_wt2[k*G4 + c*4 + g] = W_hh[g*H+c][k]
__global__ void whht_kernel(const float* __restrict__ W_hh) {
    int c = blockIdx.x * 256 + threadIdx.x;
    int k = blockIdx.y;
    if (c < HH) {
        float4 v;
        v.x = W_hh[(size_t)(0 * HH + c) * HH + k];
        v.y = W_hh[(size_t)(1 * HH + c) * HH + k];
        v.z = W_hh[(size_t)(2 * HH + c) * HH + k];
        v.w = W_hh[(size_t)(3 * HH + c) * HH + k];
        *(float4*)(g_wt2 + (size_t)k * G4 + c * 4) = v;
    }
}

// ------------- SGEMM C = A(Mx768)*B(Nx768)^T, 128x128x8 double-buffered -------------
// EPI 0: gate-interleaved store + bias (x projection)
// EPI 1: fused per-row max / sumexp partials + target logit
template<int EPI>
__global__ void __launch_bounds__(256) sgemm_nt(const float* __restrict__ Bm,
                                               int M, int N,
                                               const float* __restrict__ bias) {
    const float* Am = (EPI == 0) ? g_din : g_hs;
    __shared__ float As[2][8][132];
    __shared__ float Bs[2][8][132];
    __shared__ float red[128][17];
    __shared__ float rowmax[128];

    const int tid = threadIdx.x;
    const int bm = blockIdx.y, bn = blockIdx.x;
    const int ty = tid >> 4, tx = tid & 15;
    const int m0 = ty * 8, n0 = tx * 8;
    const int lr = tid >> 1;
    const int lk = (tid & 1) * 4;

    float acc[8][8];
    #pragma unroll
    for (int i = 0; i < 8; i++)
        #pragma unroll
        for (int j = 0; j < 8; j++) acc[i][j] = 0.f;

    const float4 z4 = make_float4(0.f, 0.f, 0.f, 0.f);
    float4 aR, bR;
    {
        int gm = bm * 128 + lr, gn = bn * 128 + lr;
        aR = (gm < M) ? *(const float4*)(Am + (size_t)gm * HH + lk) : z4;
        bR = (gn < N) ? *(const float4*)(Bm + (size_t)gn * HH + lk) : z4;
    }
    As[0][lk+0][lr] = aR.x; As[0][lk+1][lr] = aR.y; As[0][lk+2][lr] = aR.z; As[0][lk+3][lr] = aR.w;
    Bs[0][lk+0][lr] = bR.x; Bs[0][lk+1][lr] = bR.y; Bs[0][lk+2][lr] = bR.z; Bs[0][lk+3][lr] = bR.w;
    __syncthreads();

    const int KT = HH / 8;   // 96
    for (int kt = 0; kt < KT; kt++) {
        int cur = kt & 1;
        if (kt + 1 < KT) {
            int gk = (kt + 1) * 8 + lk;
            int gm = bm * 128 + lr, gn = bn * 128 + lr;
            aR = (gm < M) ? *(const float4*)(Am + (size_t)gm * HH + gk) : z4;
            bR = (gn < N) ? *(const float4*)(Bm + (size_t)gn * HH + gk) : z4;
        }
        #pragma unroll
        for (int kk = 0; kk < 8; kk++) {
            float4 a0 = *(const float4*)&As[cur][kk][m0];
            float4 a1 = *(const float4*)&As[cur][kk][m0 + 4];
            float4 b0 = *(const float4*)&Bs[cur][kk][n0];
            float4 b1 = *(const float4*)&Bs[cur][kk][n0 + 4];
            float av[8] = {a0.x,a0.y,a0.z,a0.w,a1.x,a1.y,a1.z,a1.w};
            float bv[8] = {b0.x,b0.y,b0.z,b0.w,b1.x,b1.y,b1.z,b1.w};
            #pragma unroll
            for (int i = 0; i < 8; i++)
                #pragma unroll
                for (int j = 0; j < 8; j++) acc[i][j] += av[i] * bv[j];
        }
        if (kt + 1 < KT) {
            int nxt = cur ^ 1;
            As[nxt][lk+0][lr] = aR.x; As[nxt][lk+1][lr] = aR.y; As[nxt][lk+2][lr] = aR.z; As[nxt][lk+3][lr] = aR.w;
            Bs[nxt][lk+0][lr] = bR.x; Bs[nxt][lk+1][lr] = bR.y; Bs[nxt][lk+2][lr] = bR.z; Bs[nxt][lk+3][lr] = bR.w;
            __syncthreads();
        }
    }

    if (EPI == 0) {
        #pragma unroll
        for (int i = 0; i < 8; i++) {
            int gm = bm * 128 + m0 + i;
            if (gm >= M) continue;
            #pragma unroll
            for (int j = 0; j < 8; j++) {
                int gn = bn * 128 + n0 + j;
                if (gn < N)
                    g_xih[(size_t)gm * G4 + (gn % HH) * 4 + (gn / HH)] = acc[i][j] + bias[gn];
            }
        }
    } else {
        float bvals[8]; int tg[8];
        #pragma unroll
        for (int j = 0; j < 8; j++) {
            int gn = bn * 128 + n0 + j;
            bvals[j] = (gn < N) ? bias[gn] : 0.f;
        }
        #pragma unroll
        for (int i = 0; i < 8; i++) {
            int gm = bm * 128 + m0 + i;
            tg[i] = (gm < M) ? g_tgt[gm] : -1;
        }
        #pragma unroll
        for (int i = 0; i < 8; i++) {
            float lm = -FLT_MAX;
            #pragma unroll
            for (int j = 0; j < 8; j++) {
                int gn = bn * 128 + n0 + j;
                if (gn < N) lm = fmaxf(lm, acc[i][j] + bvals[j]);
            }
            red[m0 + i][tx] = lm;
        }
        __syncthreads();
        if (tid < 128) {
            float rm = -FLT_MAX;
            #pragma unroll
            for (int q = 0; q < 16; q++) rm = fmaxf(rm, red[tid][q]);
            rowmax[tid] = rm;
        }
        __syncthreads();
        #pragma unroll
        for (int i = 0; i < 8; i++) {
            float rm = rowmax[m0 + i];
            float ls = 0.f;
            #pragma unroll
            for (int j = 0; j < 8; j++) {
                int gn = bn * 128 + n0 + j;
                if (gn < N) {
                    float v = acc[i][j] + bvals[j];
                    ls += expf(v - rm);
                    if (gn == tg[i]) g_tgtlog[bm * 128 + m0 + i] = v;
                }
            }
            red[m0 + i][tx] = ls;
        }
        __syncthreads();
        if (tid < 128) {
            int gm = bm * 128 + tid;
            if (gm < M) {
                float s = 0.f;
                #pragma unroll
                for (int q = 0; q < 16; q++) s += red[tid][q];
                g_pmax[(size_t)gm * NTILE2 + bn] = rowmax[tid];
                g_psum[(size_t)gm * NTILE2 + bn] = s;
            }
        }
    }
}

// ------------- persistent LSTM with grid barrier -------------
__device__ __forceinline__ void grid_barrier() {
    __syncthreads();
    if (threadIdx.x == 0) {
        unsigned g = *((volatile unsigned*)&g_bar_gen);
        unsigned prev = atomicAdd(&g_bar_cnt, 1u);
        if (prev == (unsigned)(LSTM_NB - 1)) {
            g_bar_cnt = 0u;
            __threadfence();
            atomicExch(&g_bar_gen, g + 1u);
        } else {
            while (*((volatile unsigned*)&g_bar_gen) == g) { }
        }
        __threadfence();
    }
    __syncthreads();
}

__global__ void __launch_bounds__(256, 1) lstm_kernel() {
    __shared__ float  h_sm[BB][HH];        // 24 KB
    __shared__ float4 red_w[8 * 64];       // 8 KB : [warp][col*8+b]
    int tid = threadIdx.x;
    int col = tid & 7;
    int ks  = tid >> 3;                    // 0..31
    int w   = tid >> 5;
    int gcol = blockIdx.x * 8 + col;
    int k0 = ks * 24;
    float c_st = 0.f;                      // c state, valid for tid<64 (col=tid>>3,b=tid&7)

    for (int i = tid; i < BB * HH; i += 256) ((float*)h_sm)[i] = 0.f;
    __syncthreads();

    const float4* W4 = (const float4*)g_wt2;
    for (int t = 0; t < TM1; t++) {
        float4 acc[8];
        #pragma unroll
        for (int b = 0; b < 8; b++) acc[b] = make_float4(0.f, 0.f, 0.f, 0.f);
        #pragma unroll 2
        for (int kc = 0; kc < 24; kc += 4) {
            float4 w0 = W4[(size_t)(k0 + kc + 0) * HH + gcol];
            float4 w1 = W4[(size_t)(k0 + kc + 1) * HH + gcol];
            float4 w2 = W4[(size_t)(k0 + kc + 2) * HH + gcol];
            float4 w3 = W4[(size_t)(k0 + kc + 3) * HH + gcol];
            #pragma unroll
            for (int b = 0; b < 8; b++) {
                float4 h4 = *(const float4*)&h_sm[b][k0 + kc];
                acc[b].x += h4.x*w0.x + h4.y*w1.x + h4.z*w2.x + h4.w*w3.x;
                acc[b].y += h4.x*w0.y + h4.y*w1.y + h4.z*w2.y + h4.w*w3.y;
                acc[b].z += h4.x*w0.z + h4.y*w1.z + h4.z*w2.z + h4.w*w3.z;
                acc[b].w += h4.x*w0.w + h4.y*w1.w + h4.z*w2.w + h4.w*w3.w;
            }
        }
        // reduce the 4 ks-slices that live in this warp (lanes differing in bits 3,4)
        #pragma unroll
        for (int b = 0; b < 8; b++) {
            acc[b].x += __shfl_xor_sync(0xffffffffu, acc[b].x, 8);
            acc[b].y += __shfl_xor_sync(0xffffffffu, acc[b].y, 8);
            acc[b].z += __shfl_xor_sync(0xffffffffu, acc[b].z, 8);
            acc[b].w += __shfl_xor_sync(0xffffffffu, acc[b].w, 8);
            acc[b].x += __shfl_xor_sync(0xffffffffu, acc[b].x, 16);
            acc[b].y += __shfl_xor_sync(0xffffffffu, acc[b].y, 16);
            acc[b].z += __shfl_xor_sync(0xffffffffu, acc[b].z, 16);
            acc[b].w += __shfl_xor_sync(0xffffffffu, acc[b].w, 16);
        }
        if ((tid & 31) < 8) {              // lane<8 stores all 8 b for its col
            #pragma unroll
            for (int b = 0; b < 8; b++) red_w[w * 64 + col * 8 + b] = acc[b];
        }
        __syncthreads();
        if (tid < 64) {
            int rcol = tid >> 3, rb = tid & 7;
            float4 s = make_float4(0.f, 0.f, 0.f, 0.f);
            #pragma unroll
            for (int q = 0; q < 8; q++) {
                float4 v = red_w[q * 64 + tid];
                s.x += v.x; s.y += v.y; s.z += v.z; s.w += v.w;
            }
            float4 xg = *(const float4*)(g_xih + (size_t)(t * 8 + rb) * G4
                                         + (blockIdx.x * 8 + rcol) * 4);
            float gi = s.x + xg.x, gf = s.y + xg.y, gg = s.z + xg.z, go = s.w + xg.w;
            float si = 1.f / (1.f + expf(-gi));
            float sf = 1.f / (1.f + expf(-gf));
            float so = 1.f / (1.f + expf(-go));
            c_st = sf * c_st + si * tanhf(gg);
            float h = so * tanhf(c_st);
            g_hs[(size_t)(t * 8 + rb) * HH + blockIdx.x * 8 + rcol] = h;
            __threadfence();
        }
        grid_barrier();
        if (t + 1 < TM1) {
            for (int i = tid; i < BB * HH; i += 256) {
                int b = i / HH, k = i % HH;
                h_sm[b][k] = g_hs[(size_t)(t * 8 + b) * HH + k];
            }
            __syncthreads();
        }
    }
}

// ------------- per-row logsumexp combine -------------
__global__ void rowfinal_kernel() {
    int r = blockIdx.x * 256 + threadIdx.x;
    if (r < MR) {
        float m = -FLT_MAX;
        for (int j = 0; j < NTILE2; j++) m = fmaxf(m, g_pmax[(size_t)r * NTILE2 + j]);
        float s = 0.f;
        for (int j = 0; j < NTILE2; j++)
            s += g_psum[(size_t)r * NTILE2 + j] * expf(g_pmax[(size_t)r * NTILE2 + j] - m);
        float lse = m + logf(s);
        g_tokpl[r] = (g_tgtlog[r] - lse) * g_maskt[r];
    }
}

__device__ float blk_red256(float v) {
    __shared__ float sh[256];
    int tid = threadIdx.x;
    sh[tid] = v;
    __syncthreads();
    for (int s = 128; s > 0; s >>= 1) {
        if (tid < s) sh[tid] += sh[tid + s];
        __syncthreads();
    }
    float r = sh[0];
    __syncthreads();
    return r;
}

__global__ void finalize_kernel(const int* __restrict__ amask, float* out, int out_size) {
    int tid = threadIdx.x;
    float s1 = 0.f, m1 = 0.f, s2 = 0.f, m2 = 0.f;
    for (int r = tid; r < MR; r += 256) { s1 += g_tokpl[r]; m1 += g_maskt[r]; }
    for (int i = tid; i < BB * TT; i += 256) { s2 += g_enttok[i]; m2 += (float)amask[i]; }
    s1 = blk_red256(s1);
    m1 = blk_red256(m1);
    s2 = blk_red256(s2);
    m2 = blk_red256(m2);
    if (tid == 0) out[0] = -(s1 / m1 + s2 / m2);
    if (out_size >= 1 + BB * TT) {
        for (int i = tid; i < BB * TT; i += 256) {
            int b = i >> 8, t = i & 255;
            out[1 + i] = (float)g_z[t * 8 + b];
        }
    }
}

// ------------- launch -------------
extern "C" void kernel_launch(void* const* d_in, const int* in_sizes, int n_in,
                              void* d_out, int out_size) {
    const float* x_emb  = (const float*)d_in[0];
    const float* S      = (const float*)d_in[1];
    const float* emb    = (const float*)d_in[2];
    const float* W_ih   = (const float*)d_in[3];
    const float* W_hh   = (const float*)d_in[4];
    const float* b_lstm = (const float*)d_in[5];
    const float* W_out  = (const float*)d_in[6];
    const float* b_out  = (const float*)d_in[7];
    const float* gumbel = (const float*)d_in[8];
    const int*   x      = (const int*)d_in[9];
    const int*   amask  = (const int*)d_in[10];
    float* out = (float*)d_out;

    fillz_kernel<<<(out_size + 255) / 256, 256>>>(out, out_size);
    emission_kernel<<<BB * TT, 128>>>(x_emb, S, amask);
    trans_kernel<<<1, 512>>>(S);
    crf_kernel<<<1, 256>>>(gumbel);
    decin_kernel<<<MR, 256>>>(S, emb, x, amask);
    whht_kernel<<<dim3(3, HH), 256>>>(W_hh);
    sgemm_nt<0><<<dim3(G4 / 128, 16), 256>>>(W_ih, MR, G4, b_lstm);
    lstm_kernel<<<LSTM_NB, 256>>>();
    sgemm_nt<1><<<dim3(NTILE2, 16), 256>>>(W_out, MR, VV, b_out);
    rowfinal_kernel<<<8, 256>>>();
    finalize_kernel<<<1, 256>>>(amask, out, out_size);
}

// round 3
// speedup vs baseline: 1.5449x; 1.5449x over previous
#include <cuda_runtime.h>
#include <cuda_bf16.h>
#include <math.h>
#include <float.h>
#include <stdint.h>

#define BB 8
#define TT 256
#define KK 20
#define HH 768
#define VV 30522
#define G4 3072
#define TM1 255
#define MR 2040          // (T-1)*B
#define NTILE2 239       // ceil(V/128)
#define NPAD (NTILE2*128)   // 30592
#define MPAD 2048
#define LSTM_NB 96
#define TAU_C 1.0f

// ------------- static device scratch -------------
__device__ float g_em[TT*BB*KK];
__device__ float g_trans[KK*KK];
__device__ float g_alphas[TT*BB*KK];
__device__ float g_relaxed[TT*BB*KK];
__device__ int   g_z[TT*BB];
__device__ float g_enttok[BB*TT];
__device__ float g_din[MR*HH];
__device__ float g_xih[(size_t)MR*G4];
__device__ float g_wt2[HH*G4];
__device__ float g_hs[MR*HH];
__device__ __nv_bfloat16 g_hsb[(size_t)MPAD*HH];     // pad rows stay zero
__device__ __nv_bfloat16 g_wob[(size_t)NPAD*HH];     // pad rows stay zero
__device__ float g_pmax[(size_t)MR*NTILE2];
__device__ float g_psum[(size_t)MR*NTILE2];
__device__ float g_tgtlog[MR];
__device__ float g_tokpl[MR];
__device__ int   g_tgt[MR];
__device__ float g_maskt[MR];
__device__ unsigned g_bar_cnt;
__device__ unsigned g_bar_gen;

// ------------- misc small kernels -------------
__global__ void fillz_kernel(float* out, int n) {
    int i = blockIdx.x * 256 + threadIdx.x;
    if (i < n) out[i] = 0.f;
}

__global__ void conv_wout_kernel(const float* __restrict__ W) {
    int i = blockIdx.x * 256 + threadIdx.x;
    int n = VV * HH / 4;
    if (i < n) {
        float4 v = ((const float4*)W)[i];
        __nv_bfloat162* dst = (__nv_bfloat162*)g_wob;
        dst[i * 2 + 0] = __floats2bfloat162_rn(v.x, v.y);
        dst[i * 2 + 1] = __floats2bfloat162_rn(v.z, v.w);
    }
}

// emission[t][b][k] + entropy token
__global__ void emission_kernel(const float* __restrict__ x_emb,
                                const float* __restrict__ S,
                                const int* __restrict__ amask) {
    __shared__ float xs[HH];
    __shared__ float es[KK];
    int bt = blockIdx.x;          // b*T + t
    int b = bt >> 8, t = bt & 255;
    int tid = threadIdx.x;
    for (int i = tid; i < HH; i += 128) xs[i] = x_emb[(size_t)bt * HH + i];
    __syncthreads();
    int w = tid >> 5, lane = tid & 31;
    for (int k = w; k < KK; k += 4) {
        float s = 0.f;
        for (int i = lane; i < HH; i += 32) s += xs[i] * S[k * HH + i];
        #pragma unroll
        for (int o = 16; o; o >>= 1) s += __shfl_xor_sync(0xffffffffu, s, o);
        if (lane == 0) { g_em[(t * 8 + b) * KK + k] = s; es[k] = s; }
    }
    __syncthreads();
    if (tid == 0) {
        float m = -FLT_MAX;
        #pragma unroll
        for (int k = 0; k < KK; k++) m = fmaxf(m, es[k]);
        float ss = 0.f, dot = 0.f;
        #pragma unroll
        for (int k = 0; k < KK; k++) {
            float e = __expf(es[k] - m);
            ss += e; dot += es[k] * e;
        }
        float lse = m + __logf(ss);
        g_enttok[bt] = (lse - dot / ss) * (float)amask[bt];
    }
}

__global__ void trans_kernel(const float* __restrict__ S) {
    int idx = threadIdx.x;
    if (idx < KK * KK) {
        int i = idx / KK, j = idx % KK;
        float s = 0.f;
        for (int h = 0; h < HH; h++) s += S[i * HH + h] * S[j * HH + h];
        g_trans[idx] = s;
    }
}

// CRF forward (640 threads, 4-lane split over inner K) + relaxed backward (256 threads)
__global__ void crf_kernel(const float* __restrict__ gumbel) {
    __shared__ float sa[BB*KK];
    __shared__ float st[KK*KK];
    int tid = threadIdx.x;
    for (int i = tid; i < KK * KK; i += 640) st[i] = g_trans[i];
    if (tid < BB * KK) { float v = g_em[tid]; sa[tid] = v; g_alphas[tid] = v; }
    __syncthreads();
    int pr = tid >> 2, sub = tid & 3;       // pr in [0,160)
    int b = pr / KK, j = pr % KK;
    int i0 = sub * 5;
    for (int t = 1; t < TT; t++) {
        float m = -FLT_MAX;
        #pragma unroll
        for (int q = 0; q < 5; q++) m = fmaxf(m, sa[b * KK + i0 + q] + st[(i0 + q) * KK + j]);
        m = fmaxf(m, __shfl_xor_sync(0xffffffffu, m, 1));
        m = fmaxf(m, __shfl_xor_sync(0xffffffffu, m, 2));
        float s = 0.f;
        #pragma unroll
        for (int q = 0; q < 5; q++) s += __expf(sa[b * KK + i0 + q] + st[(i0 + q) * KK + j] - m);
        s += __shfl_xor_sync(0xffffffffu, s, 1);
        s += __shfl_xor_sync(0xffffffffu, s, 2);
        float v = m + __logf(s) + g_em[t * (BB*KK) + pr];
        __syncthreads();
        if (sub == 0) { sa[pr] = v; g_alphas[t * (BB*KK) + pr] = v; }
        __syncthreads();
    }
    // backward sampling: warp b handles batch b (threads < 256)
    if (tid < 256) {
        int wb = tid >> 5, lane = tid & 31;
        int znext = 0;
        for (int t = TT - 1; t >= 0; t--) {
            float a;
            if (t == TT - 1) a = (lane < KK) ? sa[wb * KK + lane] : -FLT_MAX;
            else             a = (lane < KK) ? (g_alphas[t * (BB*KK) + wb * KK + lane]
                                                + st[lane * KK + znext]) : -FLT_MAX;
            float m = a;
            #pragma unroll
            for (int o = 16; o; o >>= 1) m = fmaxf(m, __shfl_xor_sync(0xffffffffu, m, o));
            float e = (lane < KK) ? __expf(a - m) : 0.f;
            float s = e;
            #pragma unroll
            for (int o = 16; o; o >>= 1) s += __shfl_xor_sync(0xffffffffu, s, o);
            float lse = m + __logf(s);
            float gb = (lane < KK) ? gumbel[(t * BB + wb) * KK + lane] : 0.f;
            float y = (lane < KK) ? (a - lse + gb) : -FLT_MAX;
            float mv = y; int mi = (lane < KK) ? lane : 1000;
            #pragma unroll
            for (int o = 16; o; o >>= 1) {
                float ov = __shfl_xor_sync(0xffffffffu, mv, o);
                int   oi = __shfl_xor_sync(0xffffffffu, mi, o);
                if (ov > mv || (ov == mv && oi < mi)) { mv = ov; mi = oi; }
            }
            float yt = y * (1.0f / TAU_C);
            float m2 = yt;
            #pragma unroll
            for (int o = 16; o; o >>= 1) m2 = fmaxf(m2, __shfl_xor_sync(0xffffffffu, m2, o));
            float e2 = (lane < KK) ? __expf(yt - m2) : 0.f;
            float s2 = e2;
            #pragma unroll
            for (int o = 16; o; o >>= 1) s2 += __shfl_xor_sync(0xffffffffu, s2, o);
            if (lane < KK) g_relaxed[(t * BB + wb) * KK + lane] = e2 / s2;
            if (lane == 0) g_z[t * BB + wb] = mi;
            znext = mi;
        }
    }
}

// dec_in row r=t*8+b : relaxed @ S + word_emb ; also targets / masks
__global__ void decin_kernel(const float* __restrict__ S,
                             const float* __restrict__ emb,
                             const int* __restrict__ x,
                             const int* __restrict__ amask) {
    __shared__ float rs[KK];
    int r = blockIdx.x;
    int t = r >> 3, b = r & 7;
    int tid = threadIdx.x;
    if (tid < KK) rs[tid] = g_relaxed[r * KK + tid];
    if (tid == 0) {
        g_tgt[r]   = x[b * TT + t + 1];
        g_maskt[r] = (float)amask[b * TT + t + 1];
    }
    __syncthreads();
    int xid = x[b * TT + t];
    for (int h = tid; h < HH; h += 256) {
        float s = emb[(size_t)xid * HH + h];
        #pragma unroll
        for (int k = 0; k < KK; k++) s += rs[k] * S[k * HH + h];
        g_din[(size_t)r * HH + h] = s;
    }
}

// W_hh^T, gate-interleaved: g_wt2[k*G4 + c*4 + g] = W_hh[g*H+c][k]
__global__ void whht_kernel(const float* __restrict__ W_hh) {
    int c = blockIdx.x * 256 + threadIdx.x;
    int k = blockIdx.y;
    if (c < HH) {
        float4 v;
        v.x = W_hh[(size_t)(0 * HH + c) * HH + k];
        v.y = W_hh[(size_t)(1 * HH + c) * HH + k];
        v.z = W_hh[(size_t)(2 * HH + c) * HH + k];
        v.w = W_hh[(size_t)(3 * HH + c) * HH + k];
        *(float4*)(g_wt2 + (size_t)k * G4 + c * 4) = v;
    }
}

// ------------- GEMM1 fp32: g_xih = dec_in @ W_ih^T (gate-interleaved) -------------
__global__ void __launch_bounds__(256) sgemm1(const float* __restrict__ Bm,
                                              const float* __restrict__ bias) {
    const float* Am = g_din;
    const int M = MR, N = G4;
    __shared__ float As[2][8][132];
    __shared__ float Bs[2][8][132];

    const int tid = threadIdx.x;
    const int bm = blockIdx.y, bn = blockIdx.x;
    const int ty = tid >> 4, tx = tid & 15;
    const int m0 = ty * 8, n0 = tx * 8;
    const int lr = tid >> 1;
    const int lk = (tid & 1) * 4;

    float acc[8][8];
    #pragma unroll
    for (int i = 0; i < 8; i++)
        #pragma unroll
        for (int j = 0; j < 8; j++) acc[i][j] = 0.f;

    const float4 z4 = make_float4(0.f, 0.f, 0.f, 0.f);
    float4 aR, bR;
    {
        int gm = bm * 128 + lr, gn = bn * 128 + lr;
        aR = (gm < M) ? *(const float4*)(Am + (size_t)gm * HH + lk) : z4;
        bR = (gn < N) ? *(const float4*)(Bm + (size_t)gn * HH + lk) : z4;
    }
    As[0][lk+0][lr] = aR.x; As[0][lk+1][lr] = aR.y; As[0][lk+2][lr] = aR.z; As[0][lk+3][lr] = aR.w;
    Bs[0][lk+0][lr] = bR.x; Bs[0][lk+1][lr] = bR.y; Bs[0][lk+2][lr] = bR.z; Bs[0][lk+3][lr] = bR.w;
    __syncthreads();

    const int KT = HH / 8;
    for (int kt = 0; kt < KT; kt++) {
        int cur = kt & 1;
        if (kt + 1 < KT) {
            int gk = (kt + 1) * 8 + lk;
            int gm = bm * 128 + lr, gn = bn * 128 + lr;
            aR = (gm < M) ? *(const float4*)(Am + (size_t)gm * HH + gk) : z4;
            bR = (gn < N) ? *(const float4*)(Bm + (size_t)gn * HH + gk) : z4;
        }
        #pragma unroll
        for (int kk = 0; kk < 8; kk++) {
            float4 a0 = *(const float4*)&As[cur][kk][m0];
            float4 a1 = *(const float4*)&As[cur][kk][m0 + 4];
            float4 b0 = *(const float4*)&Bs[cur][kk][n0];
            float4 b1 = *(const float4*)&Bs[cur][kk][n0 + 4];
            float av[8] = {a0.x,a0.y,a0.z,a0.w,a1.x,a1.y,a1.z,a1.w};
            float bv[8] = {b0.x,b0.y,b0.z,b0.w,b1.x,b1.y,b1.z,b1.w};
            #pragma unroll
            for (int i = 0; i < 8; i++)
                #pragma unroll
                for (int j = 0; j < 8; j++) acc[i][j] += av[i] * bv[j];
        }
        if (kt + 1 < KT) {
            int nxt = cur ^ 1;
            As[nxt][lk+0][lr] = aR.x; As[nxt][lk+1][lr] = aR.y; As[nxt][lk+2][lr] = aR.z; As[nxt][lk+3][lr] = aR.w;
            Bs[nxt][lk+0][lr] = bR.x; Bs[nxt][lk+1][lr] = bR.y; Bs[nxt][lk+2][lr] = bR.z; Bs[nxt][lk+3][lr] = bR.w;
            __syncthreads();
        }
    }
    #pragma unroll
    for (int i = 0; i < 8; i++) {
        int gm = bm * 128 + m0 + i;
        if (gm >= M) continue;
        #pragma unroll
        for (int j = 0; j < 8; j++) {
            int gn = bn * 128 + n0 + j;
            g_xih[(size_t)gm * G4 + (gn % HH) * 4 + (gn / HH)] = acc[i][j] + bias[gn];
        }
    }
}

// ------------- GEMM2 bf16 tensor-core with fused logsumexp epilogue -------------
__device__ __forceinline__ void ldm_x4(uint32_t& r0, uint32_t& r1, uint32_t& r2, uint32_t& r3, uint32_t addr) {
    asm volatile("ldmatrix.sync.aligned.m8n8.x4.shared.b16 {%0,%1,%2,%3}, [%4];"
                 : "=r"(r0), "=r"(r1), "=r"(r2), "=r"(r3) : "r"(addr));
}
__device__ __forceinline__ void ldm_x2(uint32_t& r0, uint32_t& r1, uint32_t addr) {
    asm volatile("ldmatrix.sync.aligned.m8n8.x2.shared.b16 {%0,%1}, [%2];"
                 : "=r"(r0), "=r"(r1) : "r"(addr));
}
__device__ __forceinline__ void mma16816(float* d, const uint32_t* a, const uint32_t* b) {
    asm volatile("mma.sync.aligned.m16n8k16.row.col.f32.bf16.bf16.f32 "
                 "{%0,%1,%2,%3},{%4,%5,%6,%7},{%8,%9},{%0,%1,%2,%3};"
                 : "+f"(d[0]), "+f"(d[1]), "+f"(d[2]), "+f"(d[3])
                 : "r"(a[0]), "r"(a[1]), "r"(a[2]), "r"(a[3]), "r"(b[0]), "r"(b[1]));
}

#define SPITCH 40   // halves per row in smem (80B: conflict-free for ldmatrix)

__global__ void __launch_bounds__(256) gemm2_kernel(const float* __restrict__ bias) {
    __shared__ __nv_bfloat16 sA[2][128 * SPITCH];
    __shared__ __nv_bfloat16 sB[2][128 * SPITCH];
    __shared__ float redm[128][5];
    __shared__ float rmaxs[128];
    __shared__ float reds[128][5];

    const int tid = threadIdx.x, w = tid >> 5, lane = tid & 31;
    const int bm = blockIdx.y, bn = blockIdx.x;
    const int wm = w >> 2, wn = w & 3;
    const int m_base = wm * 64, n_base = wn * 32;
    const uint32_t sAu = (uint32_t)__cvta_generic_to_shared(&sA[0][0]);
    const uint32_t sBu = (uint32_t)__cvta_generic_to_shared(&sB[0][0]);
    const uint32_t BUFB = 128 * SPITCH * 2;  // bytes per buffer

    float acc[4][4][4];
    #pragma unroll
    for (int i = 0; i < 4; i++)
        #pragma unroll
        for (int j = 0; j < 4; j++)
            #pragma unroll
            for (int q = 0; q < 4; q++) acc[i][j][q] = 0.f;

    uint4 pa[2], pb[2];
    const int r0a = (tid * 2) >> 2, s0a = (tid * 2) & 3;
    const int r1a = (tid * 2 + 1) >> 2, s1a = (tid * 2 + 1) & 3;

    // prologue
    pa[0] = *(const uint4*)(g_hsb + ((size_t)(bm * 128 + r0a)) * HH + 0 + s0a * 8);
    pa[1] = *(const uint4*)(g_hsb + ((size_t)(bm * 128 + r1a)) * HH + 0 + s1a * 8);
    pb[0] = *(const uint4*)(g_wob + ((size_t)(bn * 128 + r0a)) * HH + 0 + s0a * 8);
    pb[1] = *(const uint4*)(g_wob + ((size_t)(bn * 128 + r1a)) * HH + 0 + s1a * 8);
    *(uint4*)(&sA[0][r0a * SPITCH + s0a * 8]) = pa[0];
    *(uint4*)(&sA[0][r1a * SPITCH + s1a * 8]) = pa[1];
    *(uint4*)(&sB[0][r0a * SPITCH + s0a * 8]) = pb[0];
    *(uint4*)(&sB[0][r1a * SPITCH + s1a * 8]) = pb[1];
    __syncthreads();

    const int KT = HH / 32;  // 24
    for (int kt = 0; kt < KT; kt++) {
        int cur = kt & 1;
        if (kt + 1 < KT) {
            int gk = (kt + 1) * 32;
            pa[0] = *(const uint4*)(g_hsb + ((size_t)(bm * 128 + r0a)) * HH + gk + s0a * 8);
            pa[1] = *(const uint4*)(g_hsb + ((size_t)(bm * 128 + r1a)) * HH + gk + s1a * 8);
            pb[0] = *(const uint4*)(g_wob + ((size_t)(bn * 128 + r0a)) * HH + gk + s0a * 8);
            pb[1] = *(const uint4*)(g_wob + ((size_t)(bn * 128 + r1a)) * HH + gk + s1a * 8);
        }
        uint32_t aBase = sAu + cur * BUFB;
        uint32_t bBase = sBu + cur * BUFB;
        #pragma unroll
        for (int g = 0; g < 2; g++) {
            uint32_t af[4][4], bf[4][2];
            #pragma unroll
            for (int mt = 0; mt < 4; mt++) {
                int r = m_base + mt * 16 + ((lane >> 3) & 1) * 8 + (lane & 7);
                int c = g * 16 + (lane >> 4) * 8;
                ldm_x4(af[mt][0], af[mt][1], af[mt][2], af[mt][3], aBase + (r * SPITCH + c) * 2);
            }
            #pragma unroll
            for (int nt = 0; nt < 4; nt++) {
                int r = n_base + nt * 8 + (lane & 7);
                int c = g * 16 + ((lane >> 3) & 1) * 8;
                ldm_x2(bf[nt][0], bf[nt][1], bBase + (r * SPITCH + c) * 2);
            }
            #pragma unroll
            for (int mt = 0; mt < 4; mt++)
                #pragma unroll
                for (int nt = 0; nt < 4; nt++)
                    mma16816(acc[mt][nt], af[mt], bf[nt]);
        }
        if (kt + 1 < KT) {
            int nxt = cur ^ 1;
            *(uint4*)(&sA[nxt][r0a * SPITCH + s0a * 8]) = pa[0];
            *(uint4*)(&sA[nxt][r1a * SPITCH + s1a * 8]) = pa[1];
            *(uint4*)(&sB[nxt][r0a * SPITCH + s0a * 8]) = pb[0];
            *(uint4*)(&sB[nxt][r1a * SPITCH + s1a * 8]) = pb[1];
            __syncthreads();
        }
    }

    // ---- fused logsumexp epilogue ----
    const int lq = lane >> 2;
    const int lc2 = (lane & 3) * 2;
    float bcol[4][2]; int cg[4][2]; bool cv[4][2];
    #pragma unroll
    for (int nt = 0; nt < 4; nt++)
        #pragma unroll
        for (int h = 0; h < 2; h++) {
            int c = bn * 128 + n_base + nt * 8 + lc2 + h;
            cg[nt][h] = c; cv[nt][h] = (c < VV);
            bcol[nt][h] = cv[nt][h] ? bias[c] : 0.f;
        }
    int rg[4][2], tg[4][2];
    #pragma unroll
    for (int mt = 0; mt < 4; mt++)
        #pragma unroll
        for (int h = 0; h < 2; h++) {
            rg[mt][h] = bm * 128 + m_base + mt * 16 + lq + h * 8;
            tg[mt][h] = (rg[mt][h] < MR) ? g_tgt[rg[mt][h]] : -1;
        }
    float lmax[4][2];
    #pragma unroll
    for (int mt = 0; mt < 4; mt++) { lmax[mt][0] = -FLT_MAX; lmax[mt][1] = -FLT_MAX; }
    #pragma unroll
    for (int mt = 0; mt < 4; mt++)
        #pragma unroll
        for (int nt = 0; nt < 4; nt++)
            #pragma unroll
            for (int q = 0; q < 4; q++) {
                int h = q >> 1, ch = q & 1;
                if (cv[nt][ch]) {
                    float v = acc[mt][nt][q] + bcol[nt][ch];
                    lmax[mt][h] = fmaxf(lmax[mt][h], v);
                    if (cg[nt][ch] == tg[mt][h]) g_tgtlog[rg[mt][h]] = v;
                }
            }
    #pragma unroll
    for (int mt = 0; mt < 4; mt++)
        #pragma unroll
        for (int h = 0; h < 2; h++) {
            lmax[mt][h] = fmaxf(lmax[mt][h], __shfl_xor_sync(0xffffffffu, lmax[mt][h], 1));
            lmax[mt][h] = fmaxf(lmax[mt][h], __shfl_xor_sync(0xffffffffu, lmax[mt][h], 2));
        }
    if ((lane & 3) == 0) {
        #pragma unroll
        for (int mt = 0; mt < 4; mt++)
            #pragma unroll
            for (int h = 0; h < 2; h++)
                redm[m_base + mt * 16 + lq + h * 8][wn] = lmax[mt][h];
    }
    __syncthreads();
    if (tid < 128) {
        float rm = -FLT_MAX;
        #pragma unroll
        for (int q = 0; q < 4; q++) rm = fmaxf(rm, redm[tid][q]);
        rmaxs[tid] = rm;
    }
    __syncthreads();
    float rmv[4][2];
    #pragma unroll
    for (int mt = 0; mt < 4; mt++)
        #pragma unroll
        for (int h = 0; h < 2; h++)
            rmv[mt][h] = rmaxs[m_base + mt * 16 + lq + h * 8];
    float lsum[4][2];
    #pragma unroll
    for (int mt = 0; mt < 4; mt++) { lsum[mt][0] = 0.f; lsum[mt][1] = 0.f; }
    #pragma unroll
    for (int mt = 0; mt < 4; mt++)
        #pragma unroll
        for (int nt = 0; nt < 4; nt++)
            #pragma unroll
            for (int q = 0; q < 4; q++) {
                int h = q >> 1, ch = q & 1;
                if (cv[nt][ch])
                    lsum[mt][h] += __expf(acc[mt][nt][q] + bcol[nt][ch] - rmv[mt][h]);
            }
    #pragma unroll
    for (int mt = 0; mt < 4; mt++)
        #pragma unroll
        for (int h = 0; h < 2; h++) {
            lsum[mt][h] += __shfl_xor_sync(0xffffffffu, lsum[mt][h], 1);
            lsum[mt][h] += __shfl_xor_sync(0xffffffffu, lsum[mt][h], 2);
        }
    if ((lane & 3) == 0) {
        #pragma unroll
        for (int mt = 0; mt < 4; mt++)
            #pragma unroll
            for (int h = 0; h < 2; h++)
                reds[m_base + mt * 16 + lq + h * 8][wn] = lsum[mt][h];
    }
    __syncthreads();
    if (tid < 128) {
        int gm = bm * 128 + tid;
        if (gm < MR) {
            float s = 0.f;
            #pragma unroll
            for (int q = 0; q < 4; q++) s += reds[tid][q];
            g_pmax[(size_t)gm * NTILE2 + bn] = rmaxs[tid];
            g_psum[(size_t)gm * NTILE2 + bn] = s;
        }
    }
}

// ------------- persistent LSTM with grid barrier -------------
__device__ __forceinline__ void grid_barrier() {
    __syncthreads();
    if (threadIdx.x == 0) {
        unsigned g = *((volatile unsigned*)&g_bar_gen);
        unsigned prev = atomicAdd(&g_bar_cnt, 1u);
        if (prev == (unsigned)(LSTM_NB - 1)) {
            g_bar_cnt = 0u;
            __threadfence();
            atomicExch(&g_bar_gen, g + 1u);
        } else {
            while (*((volatile unsigned*)&g_bar_gen) == g) { }
        }
        __threadfence();
    }
    __syncthreads();
}

__global__ void __launch_bounds__(256, 1) lstm_kernel() {
    __shared__ float  h_sm[BB][HH];
    __shared__ float4 red_w[8 * 64];
    int tid = threadIdx.x;
    int col = tid & 7;
    int ks  = tid >> 3;
    int w   = tid >> 5;
    int gcol = blockIdx.x * 8 + col;
    int k0 = ks * 24;
    float c_st = 0.f;

    for (int i = tid; i < BB * HH; i += 256) ((float*)h_sm)[i] = 0.f;
    __syncthreads();

    const float4* W4 = (const float4*)g_wt2;
    for (int t = 0; t < TM1; t++) {
        float4 acc[8];
        #pragma unroll
        for (int b = 0; b < 8; b++) acc[b] = make_float4(0.f, 0.f, 0.f, 0.f);
        #pragma unroll 2
        for (int kc = 0; kc < 24; kc += 4) {
            float4 w0 = W4[(size_t)(k0 + kc + 0) * HH + gcol];
            float4 w1 = W4[(size_t)(k0 + kc + 1) * HH + gcol];
            float4 w2 = W4[(size_t)(k0 + kc + 2) * HH + gcol];
            float4 w3 = W4[(size_t)(k0 + kc + 3) * HH + gcol];
            #pragma unroll
            for (int b = 0; b < 8; b++) {
                float4 h4 = *(const float4*)&h_sm[b][k0 + kc];
                acc[b].x += h4.x*w0.x + h4.y*w1.x + h4.z*w2.x + h4.w*w3.x;
                acc[b].y += h4.x*w0.y + h4.y*w1.y + h4.z*w2.y + h4.w*w3.y;
                acc[b].z += h4.x*w0.z + h4.y*w1.z + h4.z*w2.z + h4.w*w3.z;
                acc[b].w += h4.x*w0.w + h4.y*w1.w + h4.z*w2.w + h4.w*w3.w;
            }
        }
        #pragma unroll
        for (int b = 0; b < 8; b++) {
            acc[b].x += __shfl_xor_sync(0xffffffffu, acc[b].x, 8);
            acc[b].y += __shfl_xor_sync(0xffffffffu, acc[b].y, 8);
            acc[b].z += __shfl_xor_sync(0xffffffffu, acc[b].z, 8);
            acc[b].w += __shfl_xor_sync(0xffffffffu, acc[b].w, 8);
            acc[b].x += __shfl_xor_sync(0xffffffffu, acc[b].x, 16);
            acc[b].y += __shfl_xor_sync(0xffffffffu, acc[b].y, 16);
            acc[b].z += __shfl_xor_sync(0xffffffffu, acc[b].z, 16);
            acc[b].w += __shfl_xor_sync(0xffffffffu, acc[b].w, 16);
        }
        if ((tid & 31) < 8) {
            #pragma unroll
            for (int b = 0; b < 8; b++) red_w[w * 64 + col * 8 + b] = acc[b];
        }
        __syncthreads();
        if (tid < 64) {
            int rcol = tid >> 3, rb = tid & 7;
            float4 s = make_float4(0.f, 0.f, 0.f, 0.f);
            #pragma unroll
            for (int q = 0; q < 8; q++) {
                float4 v = red_w[q * 64 + tid];
                s.x += v.x; s.y += v.y; s.z += v.z; s.w += v.w;
            }
            float4 xg = *(const float4*)(g_xih + (size_t)(t * 8 + rb) * G4
                                         + (blockIdx.x * 8 + rcol) * 4);
            float gi = s.x + xg.x, gf = s.y + xg.y, gg = s.z + xg.z, go = s.w + xg.w;
            float si = 1.f / (1.f + expf(-gi));
            float sf = 1.f / (1.f + expf(-gf));
            float so = 1.f / (1.f + expf(-go));
            c_st = sf * c_st + si * tanhf(gg);
            float h = so * tanhf(c_st);
            size_t off = (size_t)(t * 8 + rb) * HH + blockIdx.x * 8 + rcol;
            g_hs[off] = h;
            g_hsb[off] = __float2bfloat16_rn(h);
            __threadfence();
        }
        grid_barrier();
        if (t + 1 < TM1) {
            for (int i = tid; i < BB * HH; i += 256) {
                int b = i / HH, k = i % HH;
                h_sm[b][k] = g_hs[(size_t)(t * 8 + b) * HH + k];
            }
            __syncthreads();
        }
    }
}

// ------------- per-row logsumexp combine + final reductions -------------
__global__ void rowfinal_kernel() {
    int r = blockIdx.x * 256 + threadIdx.x;
    if (r < MR) {
        float m = -FLT_MAX;
        for (int j = 0; j < NTILE2; j++) m = fmaxf(m, g_pmax[(size_t)r * NTILE2 + j]);
        float s = 0.f;
        for (int j = 0; j < NTILE2; j++)
            s += g_psum[(size_t)r * NTILE2 + j] * __expf(g_pmax[(size_t)r * NTILE2 + j] - m);
        float lse = m + __logf(s);
        g_tokpl[r] = (g_tgtlog[r] - lse) * g_maskt[r];
    }
}

__device__ float blk_red256(float v) {
    __shared__ float sh[256];
    int tid = threadIdx.x;
    sh[tid] = v;
    __syncthreads();
    for (int s = 128; s > 0; s >>= 1) {
        if (tid < s) sh[tid] += sh[tid + s];
        __syncthreads();
    }
    float r = sh[0];
    __syncthreads();
    return r;
}

__global__ void finalize_kernel(const int* __restrict__ amask, float* out, int out_size) {
    int tid = threadIdx.x;
    float s1 = 0.f, m1 = 0.f, s2 = 0.f, m2 = 0.f;
    for (int r = tid; r < MR; r += 256) { s1 += g_tokpl[r]; m1 += g_maskt[r]; }
    for (int i = tid; i < BB * TT; i += 256) { s2 += g_enttok[i]; m2 += (float)amask[i]; }
    s1 = blk_red256(s1);
    m1 = blk_red256(m1);
    s2 = blk_red256(s2);
    m2 = blk_red256(m2);
    if (tid == 0) out[0] = -(s1 / m1 + s2 / m2);
    if (out_size >= 1 + BB * TT) {
        for (int i = tid; i < BB * TT; i += 256) {
            int b = i >> 8, t = i & 255;
            out[1 + i] = (float)g_z[t * 8 + b];
        }
    }
}

// ------------- launch -------------
extern "C" void kernel_launch(void* const* d_in, const int* in_sizes, int n_in,
                              void* d_out, int out_size) {
    const float* x_emb  = (const float*)d_in[0];
    const float* S      = (const float*)d_in[1];
    const float* emb    = (const float*)d_in[2];
    const float* W_ih   = (const float*)d_in[3];
    const float* W_hh   = (const float*)d_in[4];
    const float* b_lstm = (const float*)d_in[5];
    const float* W_out  = (const float*)d_in[6];
    const float* b_out  = (const float*)d_in[7];
    const float* gumbel = (const float*)d_in[8];
    const int*   x      = (const int*)d_in[9];
    const int*   amask  = (const int*)d_in[10];
    float* out = (float*)d_out;

    fillz_kernel<<<(out_size + 255) / 256, 256>>>(out, out_size);
    conv_wout_kernel<<<(VV * HH / 4 + 255) / 256, 256>>>(W_out);
    emission_kernel<<<BB * TT, 128>>>(x_emb, S, amask);
    trans_kernel<<<1, 512>>>(S);
    crf_kernel<<<1, 640>>>(gumbel);
    decin_kernel<<<MR, 256>>>(S, emb, x, amask);
    whht_kernel<<<dim3(3, HH), 256>>>(W_hh);
    sgemm1<<<dim3(G4 / 128, 16), 256>>>(W_ih, b_lstm);
    lstm_kernel<<<LSTM_NB, 256>>>();
    gemm2_kernel<<<dim3(NTILE2, 16), 256>>>(b_out);
    rowfinal_kernel<<<8, 256>>>();
    finalize_kernel<<<1, 256>>>(amask, out, out_size);
}